// round 4
// baseline (speedup 1.0000x reference)
#include <cuda_runtime.h>
#include <math.h>

// ---------------- problem constants ----------------
#define DMODEL 1024
#define DSTATE 128
#define LSEQ   4096
#define NBATCH 4
#define MROWS  (NBATCH * LSEQ)   // 16384
#define LN_EPS 1e-3f

#define CHUNK  64
#define NCHUNK (LSEQ / CHUNK)    // 64

// ---------------- scratch (static device globals; no allocation) ----------------
__device__ float g_xn  [(size_t)MROWS * DMODEL];
__device__ float g_z   [(size_t)MROWS * DMODEL];
__device__ float g_y   [(size_t)MROWS * DMODEL];
__device__ float g_xs  [(size_t)MROWS * DSTATE];
__device__ float g_bsel[(size_t)MROWS * DSTATE];
__device__ float g_csel[(size_t)MROWS * DSTATE];
__device__ float g_u   [(size_t)MROWS * DSTATE];
__device__ float g_yloc[(size_t)MROWS * DSTATE];
__device__ float g_ys  [(size_t)MROWS * DSTATE];
__device__ float g_carry  [NBATCH * NCHUNK * DSTATE];
__device__ float g_instate[NBATCH * NCHUNK * DSTATE];

// ---------------- LayerNorm ----------------
__global__ void ln_kernel(const float* __restrict__ x,
                          const float* __restrict__ gamma,
                          const float* __restrict__ beta,
                          float* __restrict__ out)
{
    int row = blockIdx.x;
    const float4* xr = (const float4*)(x + (size_t)row * DMODEL);
    float4 v = xr[threadIdx.x];                 // 256 threads * 4 = 1024
    float s = v.x + v.y + v.z + v.w;
    float q = v.x * v.x + v.y * v.y + v.z * v.z + v.w * v.w;
    #pragma unroll
    for (int o = 16; o; o >>= 1) {
        s += __shfl_xor_sync(0xffffffffu, s, o);
        q += __shfl_xor_sync(0xffffffffu, q, o);
    }
    __shared__ float ss[8], sq[8];
    int w = threadIdx.x >> 5;
    if ((threadIdx.x & 31) == 0) { ss[w] = s; sq[w] = q; }
    __syncthreads();
    s = 0.f; q = 0.f;
    #pragma unroll
    for (int i = 0; i < 8; i++) { s += ss[i]; q += sq[i]; }
    float mu  = s * (1.0f / DMODEL);
    float var = q * (1.0f / DMODEL) - mu * mu;
    float inv = rsqrtf(var + LN_EPS);
    float4 gv = ((const float4*)gamma)[threadIdx.x];
    float4 bv = ((const float4*)beta)[threadIdx.x];
    float4 r;
    r.x = (v.x - mu) * inv * gv.x + bv.x;
    r.y = (v.y - mu) * inv * gv.y + bv.y;
    r.z = (v.z - mu) * inv * gv.z + bv.z;
    r.w = (v.w - mu) * inv * gv.w + bv.w;
    ((float4*)(out + (size_t)row * DMODEL))[threadIdx.x] = r;
}

// ---------------- generic tiled fp32 GEMM ----------------
// C[M,N] = A[M,K] @ B[K,N] (+ bias[N]) (+ addScale[n]*addMat[m,n]) (+ residual[m,n])
// M % 128 == 0, N % 128 == 0, K % 16 == 0
#define BM 128
#define BN 128
#define BK 16
#define TM 8
#define TN 8

__global__ __launch_bounds__(256, 2)
void gemm_kernel(const float* __restrict__ A, const float* __restrict__ B,
                 const float* __restrict__ bias,
                 const float* __restrict__ addMat, const float* __restrict__ addScale,
                 const float* __restrict__ residual,
                 float* __restrict__ C, int M, int N, int K)
{
    __shared__ __align__(16) float As[BK][BM];
    __shared__ __align__(16) float Bs[BK][BN];

    int tid  = threadIdx.x;                 // 0..255
    int row0 = blockIdx.y * BM;
    int col0 = blockIdx.x * BN;
    int tRow = tid / (BN / TN);             // 0..15
    int tCol = tid % (BN / TN);             // 0..15

    float acc[TM][TN];
    #pragma unroll
    for (int i = 0; i < TM; i++)
        #pragma unroll
        for (int j = 0; j < TN; j++) acc[i][j] = 0.f;

    int aRow = tid / 4;              // 0..63  (two rows per thread: +0, +64)
    int aCol = (tid % 4) * 4;        // 0,4,8,12
    int bRow = tid / 32;             // 0..7   (two rows per thread: +0, +8)
    int bCol = (tid % 32) * 4;

    const float* Aptr = A + (size_t)row0 * K;
    const float* Bptr = B + col0;

    for (int k0 = 0; k0 < K; k0 += BK) {
        #pragma unroll
        for (int i = 0; i < 2; i++) {
            int r = aRow + i * 64;
            float4 v = *(const float4*)(Aptr + (size_t)r * K + k0 + aCol);
            As[aCol + 0][r] = v.x;
            As[aCol + 1][r] = v.y;
            As[aCol + 2][r] = v.z;
            As[aCol + 3][r] = v.w;
        }
        #pragma unroll
        for (int i = 0; i < 2; i++) {
            int r = bRow + i * 8;
            *(float4*)&Bs[r][bCol] = *(const float4*)(Bptr + (size_t)(k0 + r) * N + bCol);
        }
        __syncthreads();

        #pragma unroll
        for (int kk = 0; kk < BK; kk++) {
            float a[TM], b[TN];
            #pragma unroll
            for (int i = 0; i < TM; i++) a[i] = As[kk][tRow * TM + i];
            #pragma unroll
            for (int j = 0; j < TN; j++) b[j] = Bs[kk][tCol * TN + j];
            #pragma unroll
            for (int i = 0; i < TM; i++)
                #pragma unroll
                for (int j = 0; j < TN; j++)
                    acc[i][j] += a[i] * b[j];
        }
        __syncthreads();
    }

    #pragma unroll
    for (int i = 0; i < TM; i++) {
        int r = row0 + tRow * TM + i;
        size_t rowOff = (size_t)r * N;
        #pragma unroll
        for (int j = 0; j < TN; j += 4) {
            int c = col0 + tCol * TN + j;
            float4 v = make_float4(acc[i][j], acc[i][j+1], acc[i][j+2], acc[i][j+3]);
            if (bias) {
                v.x += bias[c];   v.y += bias[c+1];
                v.z += bias[c+2]; v.w += bias[c+3];
            }
            if (addMat) {
                float4 m = *(const float4*)(addMat + rowOff + c);
                v.x += addScale[c]   * m.x;
                v.y += addScale[c+1] * m.y;
                v.z += addScale[c+2] * m.z;
                v.w += addScale[c+3] * m.w;
            }
            if (residual) {
                float4 rr = *(const float4*)(residual + rowOff + c);
                v.x += rr.x; v.y += rr.y; v.z += rr.z; v.w += rr.w;
            }
            *(float4*)(C + rowOff + c) = v;
        }
    }
}

// ---------------- elementwise u = xs * bsel ----------------
__global__ void mul_kernel(const float* __restrict__ a, const float* __restrict__ b,
                           float* __restrict__ o, int n4)
{
    int i = blockIdx.x * blockDim.x + threadIdx.x;
    if (i < n4) {
        float4 av = ((const float4*)a)[i];
        float4 bv = ((const float4*)b)[i];
        float4 r = make_float4(av.x*bv.x, av.y*bv.y, av.z*bv.z, av.w*bv.w);
        ((float4*)o)[i] = r;
    }
}

// ---------------- chunked linear scan: y[t] = r*y[t-1] + u[t] ----------------
// scan1: per-chunk local scan (zero initial state) + carry per chunk
__global__ void scan1_kernel(const float* __restrict__ u, const float* __restrict__ A_log,
                             float* __restrict__ yloc, float* __restrict__ carry)
{
    int b = blockIdx.x / NCHUNK;
    int c = blockIdx.x % NCHUNK;
    int s = threadIdx.x;                       // 0..127
    float r = expf(-expf(A_log[s]));

    __shared__ __align__(16) float sm[CHUNK * DSTATE];
    const float* up = u + ((size_t)b * LSEQ + (size_t)c * CHUNK) * DSTATE;
    for (int i = threadIdx.x; i < CHUNK * DSTATE / 4; i += DSTATE)
        ((float4*)sm)[i] = ((const float4*)up)[i];
    __syncthreads();

    float* yp = yloc + ((size_t)b * LSEQ + (size_t)c * CHUNK) * DSTATE;
    float acc = 0.f;
    #pragma unroll 8
    for (int i = 0; i < CHUNK; i++) {
        acc = acc * r + sm[i * DSTATE + s];
        yp[i * DSTATE + s] = acc;
    }
    carry[((size_t)b * NCHUNK + c) * DSTATE + s] = acc;
}

// scan2: sequential scan over the 64 chunk carries per (batch, state)
__global__ void scan2_kernel(const float* __restrict__ carry, const float* __restrict__ A_log,
                             float* __restrict__ instate)
{
    int b = blockIdx.x;
    int s = threadIdx.x;
    float a  = -expf(A_log[s]);
    float rC = expf(a * (float)CHUNK);
    float st = 0.f;
    for (int c = 0; c < NCHUNK; c++) {
        size_t idx = ((size_t)b * NCHUNK + c) * DSTATE + s;
        instate[idx] = st;
        st = st * rC + carry[idx];
    }
}

// scan3: inject incoming chunk state, then multiply by C_sel -> y_state
__global__ void scan3_kernel(const float* __restrict__ yloc, const float* __restrict__ instate,
                             const float* __restrict__ csel, const float* __restrict__ A_log,
                             float* __restrict__ ystate)
{
    int b = blockIdx.x / NCHUNK;
    int c = blockIdx.x % NCHUNK;
    int s = threadIdx.x;
    float r = expf(-expf(A_log[s]));
    float p = instate[((size_t)b * NCHUNK + c) * DSTATE + s];

    size_t off = ((size_t)b * LSEQ + (size_t)c * CHUNK) * DSTATE;
    const float* yp = yloc + off;
    const float* cp = csel + off;
    float* op = ystate + off;
    #pragma unroll 8
    for (int i = 0; i < CHUNK; i++) {
        p *= r;                                         // instate * r^{i+1}
        op[i * DSTATE + s] = (yp[i * DSTATE + s] + p) * cp[i * DSTATE + s];
    }
}

// ---------------- host ----------------
static float* sym_addr(const void* symbol)
{
    void* p = nullptr;
    cudaGetSymbolAddress(&p, symbol);
    return (float*)p;
}

extern "C" void kernel_launch(void* const* d_in, const int* in_sizes, int n_in,
                              void* d_out, int out_size)
{
    (void)in_sizes; (void)n_in; (void)out_size;
    const float* x      = (const float*)d_in[0];
    const float* ln_g   = (const float*)d_in[1];
    const float* ln_b   = (const float*)d_in[2];
    const float* W_in   = (const float*)d_in[3];
    const float* b_in   = (const float*)d_in[4];
    const float* W_xs   = (const float*)d_in[5];
    const float* W_B    = (const float*)d_in[6];
    const float* b_B    = (const float*)d_in[7];
    const float* W_C    = (const float*)d_in[8];
    const float* b_C    = (const float*)d_in[9];
    const float* A_log  = (const float*)d_in[10];
    const float* Dvec   = (const float*)d_in[11];
    const float* W_so   = (const float*)d_in[12];
    const float* W_out  = (const float*)d_in[13];
    const float* b_out  = (const float*)d_in[14];
    float* out = (float*)d_out;

    float* xn   = sym_addr(g_xn);
    float* z    = sym_addr(g_z);
    float* y    = sym_addr(g_y);
    float* xs   = sym_addr(g_xs);
    float* bsel = sym_addr(g_bsel);
    float* csel = sym_addr(g_csel);
    float* u    = sym_addr(g_u);
    float* yloc = sym_addr(g_yloc);
    float* ys   = sym_addr(g_ys);
    float* carry   = sym_addr(g_carry);
    float* instate = sym_addr(g_instate);

    // 1. LayerNorm
    ln_kernel<<<MROWS, 256>>>(x, ln_g, ln_b, xn);

    // 2. z = xn @ W_in + b_in
    gemm_kernel<<<dim3(DMODEL / BN, MROWS / BM), 256>>>(
        xn, W_in, b_in, nullptr, nullptr, nullptr, z, MROWS, DMODEL, DMODEL);

    // 3. projections to d_state
    gemm_kernel<<<dim3(DSTATE / BN, MROWS / BM), 256>>>(
        z, W_xs, nullptr, nullptr, nullptr, nullptr, xs, MROWS, DSTATE, DMODEL);
    gemm_kernel<<<dim3(DSTATE / BN, MROWS / BM), 256>>>(
        z, W_B, b_B, nullptr, nullptr, nullptr, bsel, MROWS, DSTATE, DMODEL);
    gemm_kernel<<<dim3(DSTATE / BN, MROWS / BM), 256>>>(
        z, W_C, b_C, nullptr, nullptr, nullptr, csel, MROWS, DSTATE, DMODEL);

    // 4. u = xs * bsel
    mul_kernel<<<(MROWS * DSTATE / 4 + 255) / 256, 256>>>(xs, bsel, u, MROWS * DSTATE / 4);

    // 5. causal conv with K[t,s]=r_s^t  == linear recurrence, chunked scan
    scan1_kernel<<<NBATCH * NCHUNK, DSTATE>>>(u, A_log, yloc, carry);
    scan2_kernel<<<NBATCH, DSTATE>>>(carry, A_log, instate);
    scan3_kernel<<<NBATCH * NCHUNK, DSTATE>>>(yloc, instate, csel, A_log, ys);

    // 6. y = ys @ W_so + D * z
    gemm_kernel<<<dim3(DMODEL / BN, MROWS / BM), 256>>>(
        ys, W_so, nullptr, z, Dvec, nullptr, y, MROWS, DMODEL, DSTATE);

    // 7. out = y @ W_out + b_out + x
    gemm_kernel<<<dim3(DMODEL / BN, MROWS / BM), 256>>>(
        y, W_out, b_out, nullptr, nullptr, x, out, MROWS, DMODEL, DMODEL);
}

// round 7
// speedup vs baseline: 2.0622x; 2.0622x over previous
#include <cuda_runtime.h>
#include <cuda_bf16.h>
#include <math.h>
#include <stdint.h>

// ---------------- problem constants ----------------
#define DMODEL 1024
#define DSTATE 128
#define LSEQ   4096
#define NBATCH 4
#define MROWS  (NBATCH * LSEQ)   // 16384
#define LN_EPS 1e-3f

#define CHUNK  64
#define NCHUNK (LSEQ / CHUNK)    // 64
#define NCAT   512               // padded 3*128 fused projection width

// ---------------- portable PTX helpers (sm_80+ features only) ----------------
__device__ __forceinline__ uint32_t smem_to_u32(const void* smem_ptr) {
    uint32_t addr;
    asm("{ .reg .u64 tmp; cvta.to.shared.u64 tmp, %1; cvt.u32.u64 %0, tmp; }"
        : "=r"(addr) : "l"(smem_ptr));
    return addr;
}

#define CP_ASYNC16(smem_u32, gptr) \
    asm volatile("cp.async.cg.shared.global [%0], [%1], 16;" \
        :: "r"(smem_u32), "l"(gptr) : "memory")
#define CP_COMMIT() asm volatile("cp.async.commit_group;" ::: "memory")

template <int N>
__device__ __forceinline__ void cp_wait() {
    asm volatile("cp.async.wait_group %0;" :: "n"(N) : "memory");
}

__device__ __forceinline__ void ldsm4(uint32_t addr, uint32_t* r) {
    asm volatile("ldmatrix.sync.aligned.m8n8.x4.shared.b16 {%0,%1,%2,%3}, [%4];"
        : "=r"(r[0]), "=r"(r[1]), "=r"(r[2]), "=r"(r[3]) : "r"(addr));
}

__device__ __forceinline__ void mma16816(float* c, const uint32_t* a, const uint32_t* b) {
    asm volatile(
        "mma.sync.aligned.m16n8k16.row.col.f32.bf16.bf16.f32 "
        "{%0,%1,%2,%3}, {%4,%5,%6,%7}, {%8,%9}, {%0,%1,%2,%3};"
        : "+f"(c[0]), "+f"(c[1]), "+f"(c[2]), "+f"(c[3])
        : "r"(a[0]), "r"(a[1]), "r"(a[2]), "r"(a[3]), "r"(b[0]), "r"(b[1]));
}

__device__ __forceinline__ void split1(float v, __nv_bfloat16& h, __nv_bfloat16& l) {
    h = __float2bfloat16_rn(v);
    l = __float2bfloat16_rn(v - __bfloat162float(h));
}

// ---------------- scratch (static device globals; no allocation) ----------------
__device__ float g_z   [(size_t)MROWS * DMODEL];
__device__ float g_zcat[(size_t)MROWS * NCAT];
__device__ float g_yloc[(size_t)MROWS * DSTATE];
__device__ float g_carry  [NBATCH * NCHUNK * DSTATE];
__device__ float g_instate[NBATCH * NCHUNK * DSTATE];
// bf16-split activations
__device__ __nv_bfloat16 g_xnh[(size_t)MROWS * DMODEL];
__device__ __nv_bfloat16 g_xnl[(size_t)MROWS * DMODEL];
__device__ __nv_bfloat16 g_zh [(size_t)MROWS * DMODEL];
__device__ __nv_bfloat16 g_zl [(size_t)MROWS * DMODEL];
__device__ __nv_bfloat16 g_yh [(size_t)MROWS * DMODEL];
__device__ __nv_bfloat16 g_yl [(size_t)MROWS * DMODEL];
__device__ __nv_bfloat16 g_ysh[(size_t)MROWS * DSTATE];
__device__ __nv_bfloat16 g_ysl[(size_t)MROWS * DSTATE];
// pre-transposed, bf16-split weights ([N, K] layout, K-major)
__device__ __nv_bfloat16 g_WinT_h [(size_t)DMODEL * DMODEL];
__device__ __nv_bfloat16 g_WinT_l [(size_t)DMODEL * DMODEL];
__device__ __nv_bfloat16 g_WoutT_h[(size_t)DMODEL * DMODEL];
__device__ __nv_bfloat16 g_WoutT_l[(size_t)DMODEL * DMODEL];
__device__ __nv_bfloat16 g_WsoT_h [(size_t)DMODEL * DSTATE];
__device__ __nv_bfloat16 g_WsoT_l [(size_t)DMODEL * DSTATE];
__device__ __nv_bfloat16 g_WcatT_h[(size_t)NCAT * DMODEL];
__device__ __nv_bfloat16 g_WcatT_l[(size_t)NCAT * DMODEL];
__device__ float g_bcat[NCAT];

// ---------------- LayerNorm (emits bf16 h/l split directly) ----------------
__global__ void ln_kernel(const float* __restrict__ x,
                          const float* __restrict__ gamma,
                          const float* __restrict__ beta,
                          __nv_bfloat16* __restrict__ oh,
                          __nv_bfloat16* __restrict__ ol)
{
    int row = blockIdx.x;
    const float4* xr = (const float4*)(x + (size_t)row * DMODEL);
    float4 v = xr[threadIdx.x];
    float s = v.x + v.y + v.z + v.w;
    float q = v.x * v.x + v.y * v.y + v.z * v.z + v.w * v.w;
    #pragma unroll
    for (int o = 16; o; o >>= 1) {
        s += __shfl_xor_sync(0xffffffffu, s, o);
        q += __shfl_xor_sync(0xffffffffu, q, o);
    }
    __shared__ float ss[8], sq[8];
    int w = threadIdx.x >> 5;
    if ((threadIdx.x & 31) == 0) { ss[w] = s; sq[w] = q; }
    __syncthreads();
    s = 0.f; q = 0.f;
    #pragma unroll
    for (int i = 0; i < 8; i++) { s += ss[i]; q += sq[i]; }
    float mu  = s * (1.0f / DMODEL);
    float var = q * (1.0f / DMODEL) - mu * mu;
    float inv = rsqrtf(var + LN_EPS);
    float4 gv = ((const float4*)gamma)[threadIdx.x];
    float4 bv = ((const float4*)beta)[threadIdx.x];
    float r0 = (v.x - mu) * inv * gv.x + bv.x;
    float r1 = (v.y - mu) * inv * gv.y + bv.y;
    float r2 = (v.z - mu) * inv * gv.z + bv.z;
    float r3 = (v.w - mu) * inv * gv.w + bv.w;
    __nv_bfloat16 h0, h1, h2, h3, l0, l1, l2, l3;
    split1(r0, h0, l0); split1(r1, h1, l1);
    split1(r2, h2, l2); split1(r3, h3, l3);
    size_t o = (size_t)row * DMODEL + threadIdx.x * 4;
    __nv_bfloat162 p;
    p.x = h0; p.y = h1; *(__nv_bfloat162*)(oh + o)     = p;
    p.x = h2; p.y = h3; *(__nv_bfloat162*)(oh + o + 2) = p;
    p.x = l0; p.y = l1; *(__nv_bfloat162*)(ol + o)     = p;
    p.x = l2; p.y = l3; *(__nv_bfloat162*)(ol + o + 2) = p;
}

// ---------------- weight transpose + bf16-split: W[K,N] -> T[N,K] (h,l) ----------------
__global__ void tsplit_kernel(const float* __restrict__ W,
                              __nv_bfloat16* __restrict__ Th,
                              __nv_bfloat16* __restrict__ Tl,
                              int K, int N, int rowOff, int ldT)
{
    __shared__ float t[32][33];
    int n0 = blockIdx.x * 32, k0 = blockIdx.y * 32;
    int tx = threadIdx.x, ty = threadIdx.y;          // 32 x 8
    #pragma unroll
    for (int j = 0; j < 32; j += 8)
        t[ty + j][tx] = W[(size_t)(k0 + ty + j) * N + n0 + tx];
    __syncthreads();
    #pragma unroll
    for (int j = 0; j < 32; j += 8) {
        int n = ty + j;
        float v = t[tx][n];                          // W[k0+tx][n0+n]
        __nv_bfloat16 h, l;
        split1(v, h, l);
        size_t o = (size_t)(rowOff + n0 + n) * ldT + k0 + tx;
        Th[o] = h; Tl[o] = l;
    }
}

__global__ void zpad_kernel(__nv_bfloat16* __restrict__ Th, __nv_bfloat16* __restrict__ Tl)
{
    int i = blockIdx.x * blockDim.x + threadIdx.x;   // 128*1024 elements
    if (i < 128 * DMODEL) {
        __nv_bfloat16 z = __float2bfloat16_rn(0.f);
        Th[(size_t)384 * DMODEL + i] = z;
        Tl[(size_t)384 * DMODEL + i] = z;
    }
}

__global__ void bcat_kernel(const float* __restrict__ bB, const float* __restrict__ bC,
                            float* __restrict__ bcat)
{
    int i = blockIdx.x * blockDim.x + threadIdx.x;
    float v = 0.f;
    if (i >= 128 && i < 256) v = bB[i - 128];
    else if (i >= 256 && i < 384) v = bC[i - 256];
    if (i < NCAT) bcat[i] = v;
}

// ---------------- HMMA bf16 3-split GEMM ----------------
// C = A @ B^T where A=[M,K] (Ah+Al bf16), B=[N,K] (Bh+Bl bf16, pre-transposed).
// 3-split: C ~= Ah@Bh + Ah@Bl + Al@Bh  (fp32 accumulate)
// Tile: 128x128, BK=64, 256 threads (8 warps, 2x4), double-buffered cp.async.
#define HG_BM 128
#define HG_BN 128
#define HG_BK 64
#define HG_OFF_AH 0
#define HG_OFF_AL 16384
#define HG_OFF_BH 32768
#define HG_OFF_BL 49152
#define HG_STAGE  65536
#define HG_SMEM (2 * HG_STAGE + 128)

// fill one stage: 256 threads, each does 4x16B per matrix via cp.async
__device__ __forceinline__ void hg_fill(uint32_t sbase,
                                        const __nv_bfloat16* __restrict__ Ah,
                                        const __nv_bfloat16* __restrict__ Al,
                                        const __nv_bfloat16* __restrict__ Bh,
                                        const __nv_bfloat16* __restrict__ Bl,
                                        int K, int row0, int col0, int k0, int tid)
{
    int row = tid >> 1;                    // 0..127
    int cb  = (tid & 1) * 4;               // chunk base 0 or 4 (16B chunks)
    const char* gAh = (const char*)(Ah + (size_t)(row0 + row) * K + k0);
    const char* gAl = (const char*)(Al + (size_t)(row0 + row) * K + k0);
    const char* gBh = (const char*)(Bh + (size_t)(col0 + row) * K + k0);
    const char* gBl = (const char*)(Bl + (size_t)(col0 + row) * K + k0);
    uint32_t rbase = (uint32_t)row * 128;
    #pragma unroll
    for (int i = 0; i < 4; i++) {
        int c = cb + i;
        uint32_t soff = rbase + (uint32_t)((c ^ (row & 7)) << 4);
        CP_ASYNC16(sbase + HG_OFF_AH + soff, gAh + c * 16);
        CP_ASYNC16(sbase + HG_OFF_AL + soff, gAl + c * 16);
        CP_ASYNC16(sbase + HG_OFF_BH + soff, gBh + c * 16);
        CP_ASYNC16(sbase + HG_OFF_BL + soff, gBl + c * 16);
    }
}

__global__ __launch_bounds__(256, 1)
void hmma_gemm(const __nv_bfloat16* __restrict__ Ah, const __nv_bfloat16* __restrict__ Al,
               int K,
               const __nv_bfloat16* __restrict__ Bh, const __nv_bfloat16* __restrict__ Bl,
               const float* __restrict__ bias,
               const float* __restrict__ addMat, const float* __restrict__ addScale,
               const float* __restrict__ residual,
               float* __restrict__ Cf,
               __nv_bfloat16* __restrict__ Ch, __nv_bfloat16* __restrict__ Cl,
               int ldc)
{
    extern __shared__ char dsm[];
    uint32_t sbase = (smem_to_u32(dsm) + 127u) & ~127u;

    int tid  = threadIdx.x;
    int lane = tid & 31, warp = tid >> 5;
    int wm = warp >> 2, wn = warp & 3;       // warp tile: 64x32 at (wm*64, wn*32)
    int row0 = blockIdx.y * HG_BM;
    int col0 = blockIdx.x * HG_BN;

    // per-lane ldmatrix geometry
    int r    = lane & 7;
    int tile = lane >> 3;
    int rowA_base = wm * 64 + ((tile & 1) << 3) + r;   // + mt*16
    int kcA       = tile >> 1;
    int rowB_base = wn * 32 + ((tile >> 1) << 3) + r;  // + ng*16
    int kcB       = tile & 1;

    float acc[4][4][4];
    #pragma unroll
    for (int i = 0; i < 4; i++)
        #pragma unroll
        for (int j = 0; j < 4; j++)
            #pragma unroll
            for (int k = 0; k < 4; k++) acc[i][j][k] = 0.f;

    int NS = K / HG_BK;
    hg_fill(sbase, Ah, Al, Bh, Bl, K, row0, col0, 0, tid);
    CP_COMMIT();

    for (int s = 0; s < NS; s++) {
        if (s + 1 < NS) {
            hg_fill(sbase + ((s + 1) & 1) * HG_STAGE, Ah, Al, Bh, Bl, K,
                    row0, col0, (s + 1) * HG_BK, tid);
            CP_COMMIT();
            cp_wait<1>();
        } else {
            cp_wait<0>();
        }
        __syncthreads();

        uint32_t sb = sbase + (s & 1) * HG_STAGE;
        #pragma unroll
        for (int ks = 0; ks < 4; ks++) {
            uint32_t ah[4][4], al[4][4], bh[2][4], bl[2][4];
            uint32_t koA = (uint32_t)(((ks << 1) + kcA) ^ r) << 4;
            uint32_t koB = (uint32_t)(((ks << 1) + kcB) ^ r) << 4;
            #pragma unroll
            for (int mt = 0; mt < 4; mt++) {
                uint32_t rb = (uint32_t)(rowA_base + mt * 16) * 128;
                ldsm4(sb + HG_OFF_AH + rb + koA, ah[mt]);
                ldsm4(sb + HG_OFF_AL + rb + koA, al[mt]);
            }
            #pragma unroll
            for (int ng = 0; ng < 2; ng++) {
                uint32_t rb = (uint32_t)(rowB_base + ng * 16) * 128;
                ldsm4(sb + HG_OFF_BH + rb + koB, bh[ng]);
                ldsm4(sb + HG_OFF_BL + rb + koB, bl[ng]);
            }
            #pragma unroll
            for (int mt = 0; mt < 4; mt++) {
                #pragma unroll
                for (int nt = 0; nt < 4; nt++) {
                    const uint32_t* bhp = &bh[nt >> 1][(nt & 1) * 2];
                    const uint32_t* blp = &bl[nt >> 1][(nt & 1) * 2];
                    mma16816(acc[mt][nt], ah[mt], bhp);
                    mma16816(acc[mt][nt], ah[mt], blp);
                    mma16816(acc[mt][nt], al[mt], bhp);
                }
            }
        }
        __syncthreads();
    }

    // ---------- epilogue ----------
    int mbase = row0 + wm * 64 + (lane >> 2);
    int nbase = col0 + wn * 32 + ((lane & 3) << 1);
    #pragma unroll
    for (int mt = 0; mt < 4; mt++) {
        #pragma unroll
        for (int nt = 0; nt < 4; nt++) {
            int n = nbase + nt * 8;
            float b0 = 0.f, b1 = 0.f;
            if (bias) { b0 = bias[n]; b1 = bias[n + 1]; }
            #pragma unroll
            for (int h2 = 0; h2 < 2; h2++) {
                int m = mbase + mt * 16 + h2 * 8;
                size_t off = (size_t)m * ldc + n;
                float v0 = acc[mt][nt][h2 * 2 + 0] + b0;
                float v1 = acc[mt][nt][h2 * 2 + 1] + b1;
                if (addMat) {
                    float2 mm = *(const float2*)(addMat + off);
                    v0 += addScale[n]     * mm.x;
                    v1 += addScale[n + 1] * mm.y;
                }
                if (residual) {
                    float2 rr = *(const float2*)(residual + off);
                    v0 += rr.x; v1 += rr.y;
                }
                if (Cf) { float2 o; o.x = v0; o.y = v1; *(float2*)(Cf + off) = o; }
                if (Ch) {
                    __nv_bfloat16 h0, h1, l0, l1;
                    split1(v0, h0, l0); split1(v1, h1, l1);
                    __nv_bfloat162 p;
                    p.x = h0; p.y = h1; *(__nv_bfloat162*)(Ch + off) = p;
                    p.x = l0; p.y = l1; *(__nv_bfloat162*)(Cl + off) = p;
                }
            }
        }
    }
}

// ---------------- chunked linear scan: y[t] = r*y[t-1] + xs[t]*B[t] ----------------
__global__ void scan1_kernel(const float* __restrict__ zcat, const float* __restrict__ A_log,
                             float* __restrict__ yloc, float* __restrict__ carry)
{
    int b = blockIdx.x / NCHUNK;
    int c = blockIdx.x % NCHUNK;
    int s = threadIdx.x;                             // 0..127
    float r = expf(-expf(A_log[s]));
    size_t row = (size_t)b * LSEQ + (size_t)c * CHUNK;
    const float* zp = zcat + row * NCAT;
    float* yp = yloc + row * DSTATE;
    float acc = 0.f;
    #pragma unroll 4
    for (int i = 0; i < CHUNK; i++) {
        float xs = zp[(size_t)i * NCAT + s];
        float bb = zp[(size_t)i * NCAT + 128 + s];
        acc = acc * r + xs * bb;
        yp[i * DSTATE + s] = acc;
    }
    carry[((size_t)b * NCHUNK + c) * DSTATE + s] = acc;
}

__global__ void scan2_kernel(const float* __restrict__ carry, const float* __restrict__ A_log,
                             float* __restrict__ instate)
{
    int b = blockIdx.x;
    int s = threadIdx.x;
    float a  = -expf(A_log[s]);
    float rC = expf(a * (float)CHUNK);
    float st = 0.f;
    for (int c = 0; c < NCHUNK; c++) {
        size_t idx = ((size_t)b * NCHUNK + c) * DSTATE + s;
        instate[idx] = st;
        st = st * rC + carry[idx];
    }
}

// inject chunk state, multiply by C_sel, emit ys as bf16 h/l split
__global__ void scan3_kernel(const float* __restrict__ yloc, const float* __restrict__ instate,
                             const float* __restrict__ zcat, const float* __restrict__ A_log,
                             __nv_bfloat16* __restrict__ ysh, __nv_bfloat16* __restrict__ ysl)
{
    int b = blockIdx.x / NCHUNK;
    int c = blockIdx.x % NCHUNK;
    int s = threadIdx.x;
    float r = expf(-expf(A_log[s]));
    float p = instate[((size_t)b * NCHUNK + c) * DSTATE + s];
    size_t row = (size_t)b * LSEQ + (size_t)c * CHUNK;
    const float* yp = yloc + row * DSTATE;
    const float* cp = zcat + row * NCAT + 256;       // C_sel columns
    size_t obase = row * DSTATE;
    #pragma unroll 4
    for (int i = 0; i < CHUNK; i++) {
        p *= r;
        float v = (yp[i * DSTATE + s] + p) * cp[(size_t)i * NCAT + s];
        __nv_bfloat16 h, l;
        split1(v, h, l);
        ysh[obase + i * DSTATE + s] = h;
        ysl[obase + i * DSTATE + s] = l;
    }
}

// ---------------- host ----------------
static float* sym_addr_f(const void* symbol)
{
    void* p = nullptr;
    cudaGetSymbolAddress(&p, symbol);
    return (float*)p;
}
static __nv_bfloat16* sym_addr_b(const void* symbol)
{
    void* p = nullptr;
    cudaGetSymbolAddress(&p, symbol);
    return (__nv_bfloat16*)p;
}

extern "C" void kernel_launch(void* const* d_in, const int* in_sizes, int n_in,
                              void* d_out, int out_size)
{
    (void)in_sizes; (void)n_in; (void)out_size;
    const float* x      = (const float*)d_in[0];
    const float* ln_g   = (const float*)d_in[1];
    const float* ln_b   = (const float*)d_in[2];
    const float* W_in   = (const float*)d_in[3];
    const float* b_in   = (const float*)d_in[4];
    const float* W_xs   = (const float*)d_in[5];
    const float* W_B    = (const float*)d_in[6];
    const float* b_B    = (const float*)d_in[7];
    const float* W_C    = (const float*)d_in[8];
    const float* b_C    = (const float*)d_in[9];
    const float* A_log  = (const float*)d_in[10];
    const float* Dvec   = (const float*)d_in[11];
    const float* W_so   = (const float*)d_in[12];
    const float* W_out  = (const float*)d_in[13];
    const float* b_out  = (const float*)d_in[14];
    float* out = (float*)d_out;

    float* z    = sym_addr_f(g_z);
    float* zcat = sym_addr_f(g_zcat);
    float* yloc = sym_addr_f(g_yloc);
    float* carry   = sym_addr_f(g_carry);
    float* instate = sym_addr_f(g_instate);
    float* bcat    = sym_addr_f(g_bcat);
    __nv_bfloat16* xnh = sym_addr_b(g_xnh);
    __nv_bfloat16* xnl = sym_addr_b(g_xnl);
    __nv_bfloat16* zh  = sym_addr_b(g_zh);
    __nv_bfloat16* zl  = sym_addr_b(g_zl);
    __nv_bfloat16* yh  = sym_addr_b(g_yh);
    __nv_bfloat16* yl  = sym_addr_b(g_yl);
    __nv_bfloat16* ysh = sym_addr_b(g_ysh);
    __nv_bfloat16* ysl = sym_addr_b(g_ysl);
    __nv_bfloat16* WinT_h  = sym_addr_b(g_WinT_h);
    __nv_bfloat16* WinT_l  = sym_addr_b(g_WinT_l);
    __nv_bfloat16* WoutT_h = sym_addr_b(g_WoutT_h);
    __nv_bfloat16* WoutT_l = sym_addr_b(g_WoutT_l);
    __nv_bfloat16* WsoT_h  = sym_addr_b(g_WsoT_h);
    __nv_bfloat16* WsoT_l  = sym_addr_b(g_WsoT_l);
    __nv_bfloat16* WcatT_h = sym_addr_b(g_WcatT_h);
    __nv_bfloat16* WcatT_l = sym_addr_b(g_WcatT_l);

    cudaFuncSetAttribute(hmma_gemm, cudaFuncAttributeMaxDynamicSharedMemorySize, HG_SMEM);

    dim3 tsb(32, 8);
    // weight prep: transpose + bf16 split
    tsplit_kernel<<<dim3(32, 32), tsb>>>(W_in,  WinT_h,  WinT_l,  DMODEL, DMODEL, 0,   DMODEL);
    tsplit_kernel<<<dim3(32, 32), tsb>>>(W_out, WoutT_h, WoutT_l, DMODEL, DMODEL, 0,   DMODEL);
    tsplit_kernel<<<dim3(32, 4),  tsb>>>(W_so,  WsoT_h,  WsoT_l,  DSTATE, DMODEL, 0,   DSTATE);
    tsplit_kernel<<<dim3(4, 32),  tsb>>>(W_xs,  WcatT_h, WcatT_l, DMODEL, DSTATE, 0,   DMODEL);
    tsplit_kernel<<<dim3(4, 32),  tsb>>>(W_B,   WcatT_h, WcatT_l, DMODEL, DSTATE, 128, DMODEL);
    tsplit_kernel<<<dim3(4, 32),  tsb>>>(W_C,   WcatT_h, WcatT_l, DMODEL, DSTATE, 256, DMODEL);
    zpad_kernel<<<(128 * DMODEL + 255) / 256, 256>>>(WcatT_h, WcatT_l);
    bcat_kernel<<<2, 256>>>(b_B, b_C, bcat);

    // 1. LayerNorm -> xn (bf16 split)
    ln_kernel<<<MROWS, 256>>>(x, ln_g, ln_b, xnh, xnl);

    // 2. z = xn @ W_in + b_in   (fp32 z for D-skip, bf16 split z for next GEMMs)
    hmma_gemm<<<dim3(DMODEL / HG_BN, MROWS / HG_BM), 256, HG_SMEM>>>(
        xnh, xnl, DMODEL, WinT_h, WinT_l, b_in,
        nullptr, nullptr, nullptr, z, zh, zl, DMODEL);

    // 3. fused projections: zcat = z @ [W_xs | W_B | W_C | 0] + bcat  (fp32)
    hmma_gemm<<<dim3(NCAT / HG_BN, MROWS / HG_BM), 256, HG_SMEM>>>(
        zh, zl, DMODEL, WcatT_h, WcatT_l, bcat,
        nullptr, nullptr, nullptr, zcat, nullptr, nullptr, NCAT);

    // 4-5. chunked linear scan (u = xs*Bsel fused in scan1, *C_sel + split in scan3)
    scan1_kernel<<<NBATCH * NCHUNK, DSTATE>>>(zcat, A_log, yloc, carry);
    scan2_kernel<<<NBATCH, DSTATE>>>(carry, A_log, instate);
    scan3_kernel<<<NBATCH * NCHUNK, DSTATE>>>(yloc, instate, zcat, A_log, ysh, ysl);

    // 6. y = ys @ W_so + D * z   (bf16 split y only)
    hmma_gemm<<<dim3(DMODEL / HG_BN, MROWS / HG_BM), 256, HG_SMEM>>>(
        ysh, ysl, DSTATE, WsoT_h, WsoT_l, nullptr,
        z, Dvec, nullptr, nullptr, yh, yl, DMODEL);

    // 7. out = y @ W_out + b_out + x
    hmma_gemm<<<dim3(DMODEL / HG_BN, MROWS / HG_BM), 256, HG_SMEM>>>(
        yh, yl, DMODEL, WoutT_h, WoutT_l, b_out,
        nullptr, nullptr, x, out, nullptr, nullptr, DMODEL);
}